// round 1
// baseline (speedup 1.0000x reference)
#include <cuda_runtime.h>
#include <math.h>

// Problem constants
#define E_   512
#define H_   512
#define V_   10000
#define B_   64
#define R_   49
#define T_   32          // L-1

// -------- scratch (device globals; no allocation allowed) ----------
__device__ float g_featW[B_ * R_ * H_];        // features @ attn_W[:E] + attn_b  (3136 x 512)
__device__ float g_gxx  [B_ * T_ * 3 * H_];    // emb @ W_ih[:, :E]^T + b_ih      (2048 x 1536)
__device__ float g_W2t  [H_ * H_];             // attn_W[E:, :]^T                 (512 x 512) nt layout
__device__ float g_HP   [4 * B_ * H_];         // hattn K-split partials
__device__ float g_GHP  [4 * B_ * 3 * H_];     // h @ W_hh^T partials
__device__ float g_GXP  [4 * B_ * 3 * H_];     // ctx @ W_ih[:,E:]^T partials
__device__ float g_ctx  [B_ * E_];             // attention context
__device__ float g_hist [B_ * T_ * H_];        // all h_t (rows m = b*32+t)
__device__ float g_zero [B_ * H_];             // h0 == 0 (never written)

// ====================================================================
// Transpose attn_W[512:1024, :] -> W2t[j][k] = attn_W[(512+k)*512 + j]
// ====================================================================
__global__ void k_transpose_w2(const float* __restrict__ attn_W)
{
    __shared__ float tile[32][33];
    int bx = blockIdx.x, by = blockIdx.y;
    int tx = threadIdx.x, ty = threadIdx.y;     // (32, 8)
#pragma unroll
    for (int i = 0; i < 4; i++) {
        int k = by * 32 + ty + i * 8;
        int j = bx * 32 + tx;
        tile[ty + i * 8][tx] = attn_W[(512 + k) * 512 + j];
    }
    __syncthreads();
#pragma unroll
    for (int i = 0; i < 4; i++) {
        int j = bx * 32 + ty + i * 8;
        int k = by * 32 + tx;
        g_W2t[j * 512 + k] = tile[tx][ty + i * 8];
    }
}

// ====================================================================
// Tiled SGEMM  C[M,N] = A[M,K] @ B[K,N] + bias[N]
//   mode==0 : A = Aext (features), C = g_featW
//   mode==1 : A = g_hist,          C = Cext (d_out)
// 64x64 block tile, 256 threads, 4x4 per thread, K-chunk 16.
// Requires M%64==0, K%16==0. N guarded.
// ====================================================================
__global__ void __launch_bounds__(256)
k_sgemm_nn(int mode, const float* __restrict__ Aext, const float* __restrict__ B,
           const float* __restrict__ bias, float* __restrict__ Cext,
           int M, int N, int K, int lda, int ldb, int ldc)
{
    const float* A = (mode == 1) ? g_hist : Aext;
    float* C = (mode == 0) ? g_featW : Cext;

    __shared__ __align__(16) float As[16][68];
    __shared__ __align__(16) float Bs[16][68];

    int tid = threadIdx.x;
    int m0 = blockIdx.x * 64;
    int n0 = blockIdx.y * 64;
    int tx = tid & 15, ty = tid >> 4;

    int am = tid >> 2;              // 0..63
    int ak = (tid & 3) * 4;         // 0,4,8,12
    int bcol = tid & 63;
    int brow = tid >> 6;            // 0..3

    float acc[4][4];
#pragma unroll
    for (int i = 0; i < 4; i++)
#pragma unroll
        for (int j = 0; j < 4; j++) acc[i][j] = 0.f;

    for (int k0 = 0; k0 < K; k0 += 16) {
        float4 av = *(const float4*)(A + (long)(m0 + am) * lda + k0 + ak);
        As[ak + 0][am] = av.x; As[ak + 1][am] = av.y;
        As[ak + 2][am] = av.z; As[ak + 3][am] = av.w;
#pragma unroll
        for (int it = 0; it < 4; it++) {
            int kr = brow + it * 4;
            float v = 0.f;
            if (n0 + bcol < N) v = B[(long)(k0 + kr) * ldb + n0 + bcol];
            Bs[kr][bcol] = v;
        }
        __syncthreads();
#pragma unroll
        for (int kk = 0; kk < 16; kk++) {
            float4 a = *(const float4*)&As[kk][ty * 4];
            float4 b = *(const float4*)&Bs[kk][tx * 4];
            float ar[4] = {a.x, a.y, a.z, a.w};
            float br[4] = {b.x, b.y, b.z, b.w};
#pragma unroll
            for (int i = 0; i < 4; i++)
#pragma unroll
                for (int j = 0; j < 4; j++)
                    acc[i][j] = fmaf(ar[i], br[j], acc[i][j]);
        }
        __syncthreads();
    }
#pragma unroll
    for (int i = 0; i < 4; i++) {
        int row = m0 + ty * 4 + i;
#pragma unroll
        for (int j = 0; j < 4; j++) {
            int col = n0 + tx * 4 + j;
            if (col < N) C[(long)row * ldc + col] = acc[i][j] + bias[col];
        }
    }
}

// ====================================================================
// Gathered SGEMM-NT for gx_x:
//   C[m, n] = embed[captions[b,t]] . W_ih[n, 0:512] + b_ih[n],  m = b*32+t
// M=2048, N=1536, K=512, ldb=1024. C = g_gxx.
// ====================================================================
__global__ void __launch_bounds__(256)
k_gxx_gemm(const float* __restrict__ embed, const int* __restrict__ captions,
           const float* __restrict__ W_ih, const float* __restrict__ b_ih)
{
    __shared__ __align__(16) float As[16][68];
    __shared__ __align__(16) float Bs[16][68];

    int tid = threadIdx.x;
    int m0 = blockIdx.x * 64;
    int n0 = blockIdx.y * 64;
    int tx = tid & 15, ty = tid >> 4;

    int rr = tid >> 2;              // 0..63 (row for A and B tiles)
    int kq = (tid & 3) * 4;

    // gather base for A row
    int m = m0 + rr;
    int bb = m >> 5;                // /32
    int tt = m & 31;
    const float* arow = embed + (long)captions[bb * 33 + tt] * 512;
    const float* brow = W_ih + (long)(n0 + rr) * 1024;   // first 512 cols = x-part

    float acc[4][4];
#pragma unroll
    for (int i = 0; i < 4; i++)
#pragma unroll
        for (int j = 0; j < 4; j++) acc[i][j] = 0.f;

    for (int k0 = 0; k0 < 512; k0 += 16) {
        float4 av = *(const float4*)(arow + k0 + kq);
        As[kq + 0][rr] = av.x; As[kq + 1][rr] = av.y;
        As[kq + 2][rr] = av.z; As[kq + 3][rr] = av.w;
        float4 bv = *(const float4*)(brow + k0 + kq);
        Bs[kq + 0][rr] = bv.x; Bs[kq + 1][rr] = bv.y;
        Bs[kq + 2][rr] = bv.z; Bs[kq + 3][rr] = bv.w;
        __syncthreads();
#pragma unroll
        for (int kk = 0; kk < 16; kk++) {
            float4 a = *(const float4*)&As[kk][ty * 4];
            float4 b = *(const float4*)&Bs[kk][tx * 4];
            float ar[4] = {a.x, a.y, a.z, a.w};
            float br[4] = {b.x, b.y, b.z, b.w};
#pragma unroll
            for (int i = 0; i < 4; i++)
#pragma unroll
                for (int j = 0; j < 4; j++)
                    acc[i][j] = fmaf(ar[i], br[j], acc[i][j]);
        }
        __syncthreads();
    }
#pragma unroll
    for (int i = 0; i < 4; i++) {
        int row = m0 + ty * 4 + i;
#pragma unroll
        for (int j = 0; j < 4; j++) {
            int col = n0 + tx * 4 + j;
            g_gxx[(long)row * 1536 + col] = acc[i][j] + b_ih[col];
        }
    }
}

// ====================================================================
// Skinny NT GEMMs for the sequential step (M = 64 = batch, K-split = 4).
//  mode 0 (grid.x = 128): bx<32  -> hattn partial: A=h_prev, B=g_W2t, N=512
//                         bx>=32 -> GH partial:    A=h_prev, B=W_hh,  N=1536
//  mode 1 (grid.x = 96) :          GX partial:    A=g_ctx,  B=W_ih[:,512:], N=1536
// ====================================================================
__global__ void __launch_bounds__(256)
k_skinny(int mode, int t, const float* __restrict__ W_hh, const float* __restrict__ W_ih)
{
    const float* hA = (t == 0) ? g_zero : (g_hist + (long)(t - 1) * 512);
    int hstride = (t == 0) ? 512 : (T_ * 512);

    const float* A; int astride;
    const float* Bmat; int ldb;
    float* Cout; int ldc; int n0; int ks;

    if (mode == 0) {
        int bx = blockIdx.x;
        if (bx < 32) {
            int nt = bx & 7; ks = bx >> 3;
            A = hA; astride = hstride;
            Bmat = g_W2t; ldb = 512;
            Cout = g_HP + ks * (B_ * 512); ldc = 512; n0 = nt * 64;
        } else {
            int b2 = bx - 32;
            int nt = b2 % 24; ks = b2 / 24;
            A = hA; astride = hstride;
            Bmat = W_hh; ldb = 512;
            Cout = g_GHP + ks * (B_ * 1536); ldc = 1536; n0 = nt * 64;
        }
    } else {
        int nt = blockIdx.x % 24; ks = blockIdx.x / 24;
        A = g_ctx; astride = 512;
        Bmat = W_ih + 512; ldb = 1024;        // context part of W_ih rows
        Cout = g_GXP + ks * (B_ * 1536); ldc = 1536; n0 = nt * 64;
    }
    int kbase = ks * 128;

    __shared__ __align__(16) float As[16][68];
    __shared__ __align__(16) float Bs[16][68];

    int tid = threadIdx.x;
    int tx = tid & 15, ty = tid >> 4;
    int rr = tid >> 2;
    int kq = (tid & 3) * 4;

    float acc[4][4];
#pragma unroll
    for (int i = 0; i < 4; i++)
#pragma unroll
        for (int j = 0; j < 4; j++) acc[i][j] = 0.f;

    for (int kc = 0; kc < 8; kc++) {
        int k0 = kbase + kc * 16;
        float4 av = *(const float4*)(A + (long)rr * astride + k0 + kq);
        As[kq + 0][rr] = av.x; As[kq + 1][rr] = av.y;
        As[kq + 2][rr] = av.z; As[kq + 3][rr] = av.w;
        float4 bv = *(const float4*)(Bmat + (long)(n0 + rr) * ldb + k0 + kq);
        Bs[kq + 0][rr] = bv.x; Bs[kq + 1][rr] = bv.y;
        Bs[kq + 2][rr] = bv.z; Bs[kq + 3][rr] = bv.w;
        __syncthreads();
#pragma unroll
        for (int kk = 0; kk < 16; kk++) {
            float4 a = *(const float4*)&As[kk][ty * 4];
            float4 b = *(const float4*)&Bs[kk][tx * 4];
            float ar[4] = {a.x, a.y, a.z, a.w};
            float br[4] = {b.x, b.y, b.z, b.w};
#pragma unroll
            for (int i = 0; i < 4; i++)
#pragma unroll
                for (int j = 0; j < 4; j++)
                    acc[i][j] = fmaf(ar[i], br[j], acc[i][j]);
        }
        __syncthreads();
    }
#pragma unroll
    for (int i = 0; i < 4; i++) {
        int row = ty * 4 + i;                      // m in [0,64)
#pragma unroll
        for (int j = 0; j < 4; j++) {
            int col = n0 + tx * 4 + j;
            Cout[(long)row * ldc + col] = acc[i][j];
        }
    }
}

// ====================================================================
// Attention: sum hattn partials, scores = v_w . tanh(featW + hattn),
// softmax over R=49, context = attn @ features.  grid = 64 (one block per b)
// ====================================================================
__global__ void __launch_bounds__(256)
k_attn(const float* __restrict__ features, const float* __restrict__ v_w)
{
    int b = blockIdx.x;
    int tid = threadIdx.x;
    __shared__ float hat[512];
    __shared__ float vw[512];
    __shared__ float sc[64];

    for (int j = tid; j < 512; j += 256) {
        float s = g_HP[0 * B_ * 512 + b * 512 + j]
                + g_HP[1 * B_ * 512 + b * 512 + j]
                + g_HP[2 * B_ * 512 + b * 512 + j]
                + g_HP[3 * B_ * 512 + b * 512 + j];
        hat[j] = s;
        vw[j] = v_w[j];
    }
    __syncthreads();

    int warp = tid >> 5, lane = tid & 31;
    for (int r = warp; r < R_; r += 8) {
        const float* fw = g_featW + (long)(b * R_ + r) * 512;
        float p = 0.f;
        for (int j = lane; j < 512; j += 32)
            p += tanhf(fw[j] + hat[j]) * vw[j];
#pragma unroll
        for (int o = 16; o; o >>= 1) p += __shfl_xor_sync(0xffffffffu, p, o);
        if (lane == 0) sc[r] = p;
    }
    __syncthreads();

    if (tid < 32) {
        float s0 = (tid < R_) ? sc[tid] : -1e30f;
        float s1 = (tid + 32 < R_) ? sc[tid + 32] : -1e30f;
        float m = fmaxf(s0, s1);
#pragma unroll
        for (int o = 16; o; o >>= 1) m = fmaxf(m, __shfl_xor_sync(0xffffffffu, m, o));
        float e0 = (tid < R_) ? expf(s0 - m) : 0.f;
        float e1 = (tid + 32 < R_) ? expf(s1 - m) : 0.f;
        float s = e0 + e1;
#pragma unroll
        for (int o = 16; o; o >>= 1) s += __shfl_xor_sync(0xffffffffu, s, o);
        float inv = 1.f / s;
        if (tid < R_) sc[tid] = e0 * inv;
        if (tid + 32 < R_) sc[tid + 32] = e1 * inv;
    }
    __syncthreads();

    for (int j = tid; j < 512; j += 256) {
        const float* fb = features + (long)b * R_ * 512 + j;
        float acc = 0.f;
#pragma unroll 7
        for (int r = 0; r < R_; r++) acc = fmaf(sc[r], fb[r * 512], acc);
        g_ctx[b * 512 + j] = acc;
    }
}

// ====================================================================
// Gate combine: sum GH/GX partials, GRU update, write h_t into g_hist.
// grid = 64 (b), 512 threads (j)
// ====================================================================
__global__ void __launch_bounds__(512)
k_combine(int t, const float* __restrict__ b_hh)
{
    int b = blockIdx.x;
    int j = threadIdx.x;
    int m = b * T_ + t;

    const float* hprev = (t == 0) ? g_zero : (g_hist + (long)(t - 1) * 512);
    int hstride = (t == 0) ? 512 : (T_ * 512);

    float ghr = 0.f, ghz = 0.f, ghn = 0.f, gxr = 0.f, gxz = 0.f, gxn = 0.f;
#pragma unroll
    for (int ks = 0; ks < 4; ks++) {
        const float* gh = g_GHP + ks * (B_ * 1536) + b * 1536;
        const float* gx = g_GXP + ks * (B_ * 1536) + b * 1536;
        ghr += gh[j];        gxr += gx[j];
        ghz += gh[512 + j];  gxz += gx[512 + j];
        ghn += gh[1024 + j]; gxn += gx[1024 + j];
    }
    const float* gxx = g_gxx + (long)m * 1536;
    float xr = gxx[j] + gxr;
    float xz = gxx[512 + j] + gxz;
    float xn = gxx[1024 + j] + gxn;
    float hr = ghr + b_hh[j];
    float hz = ghz + b_hh[512 + j];
    float hn = ghn + b_hh[1024 + j];

    float r = 1.f / (1.f + expf(-(xr + hr)));
    float z = 1.f / (1.f + expf(-(xz + hz)));
    float n = tanhf(xn + r * hn);
    float hp = hprev[(long)b * hstride + j];
    g_hist[(long)m * 512 + j] = (1.f - z) * n + z * hp;
}

// ====================================================================
extern "C" void kernel_launch(void* const* d_in, const int* in_sizes, int n_in,
                              void* d_out, int out_size)
{
    const float* features = (const float*)d_in[0];
    const int*   captions = (const int*)d_in[1];
    const float* embed    = (const float*)d_in[2];
    const float* attn_W   = (const float*)d_in[3];
    const float* attn_b   = (const float*)d_in[4];
    const float* v_w      = (const float*)d_in[5];
    const float* W_ih     = (const float*)d_in[6];
    const float* W_hh     = (const float*)d_in[7];
    const float* b_ih     = (const float*)d_in[8];
    const float* b_hh     = (const float*)d_in[9];
    const float* fc_W     = (const float*)d_in[10];
    const float* fc_b     = (const float*)d_in[11];
    float* out = (float*)d_out;

    // W2 transpose (nt layout for skinny GEMM)
    k_transpose_w2<<<dim3(16, 16), dim3(32, 8)>>>(attn_W);

    // featW = features @ attn_W[:512] + attn_b   (3136 x 512, K=512)
    k_sgemm_nn<<<dim3(49, 8), 256>>>(0, features, attn_W, attn_b, nullptr,
                                     3136, 512, 512, 512, 512, 512);

    // gx_x = gather(embed, captions) @ W_ih[:, :512]^T + b_ih  (2048 x 1536)
    k_gxx_gemm<<<dim3(32, 24), 256>>>(embed, captions, W_ih, b_ih);

    // sequential scan
    for (int t = 0; t < T_; t++) {
        k_skinny<<<128, 256>>>(0, t, W_hh, W_ih);     // hattn + GH partials
        k_attn<<<64, 256>>>(features, v_w);           // softmax attention -> ctx
        k_skinny<<<96, 256>>>(1, t, W_hh, W_ih);      // GX partials
        k_combine<<<64, 512>>>(t, b_hh);              // GRU update -> hist[t]
    }

    // out = hist @ fc_W + fc_b   (2048 x 10000, K=512)
    k_sgemm_nn<<<dim3(32, 157), 256>>>(1, nullptr, fc_W, fc_b, out,
                                       2048, 10000, 512, 512, 10000, 10000);
}